// round 3
// baseline (speedup 1.0000x reference)
#include <cuda_runtime.h>
#include <math.h>
#include <stdint.h>

#define BB 4
#define TT 4096
#define CC 1024
#define HH 64

// Scratch for projected q,k,v  (12 MB total, __device__ globals per harness rules)
__device__ float g_q[(size_t)BB * TT * HH];
__device__ float g_k[(size_t)BB * TT * HH];
__device__ float g_v[(size_t)BB * TT * HH];

// ---------------------------------------------------------------------------
// Kernel 1: fused QKV projection.  x:[B*T, C] @ W{k,q,v}:[C, H] -> [B*T, H]
// Grid: 256 blocks x 64 rows. Block: 256 threads (16x16), 4x4 micro-tile,
// 3 accumulators per thread element (k,q,v share the x operand).
// ---------------------------------------------------------------------------
#define PROJ_ROWS 64
#define PROJ_KC   32

__global__ __launch_bounds__(256) void proj_kernel(
    const float* __restrict__ x,
    const float* __restrict__ Wk,
    const float* __restrict__ Wq,
    const float* __restrict__ Wv)
{
    __shared__ float Xs[PROJ_ROWS][PROJ_KC + 1];
    __shared__ float Ws_k[PROJ_KC][HH + 1];
    __shared__ float Ws_q[PROJ_KC][HH + 1];
    __shared__ float Ws_v[PROJ_KC][HH + 1];

    const int tid = threadIdx.x;
    const int tx  = tid & 15;
    const int ty  = tid >> 4;
    const int row0 = blockIdx.x * PROJ_ROWS;

    float ak[4][4], aq[4][4], av[4][4];
#pragma unroll
    for (int r = 0; r < 4; r++)
#pragma unroll
        for (int j = 0; j < 4; j++) { ak[r][j] = 0.f; aq[r][j] = 0.f; av[r][j] = 0.f; }

    for (int kc = 0; kc < CC; kc += PROJ_KC) {
        // Load X tile: 64x32 (coalesced)
#pragma unroll
        for (int idx = tid; idx < PROJ_ROWS * PROJ_KC; idx += 256) {
            int i = idx >> 5;
            int c = idx & 31;
            Xs[i][c] = x[(size_t)(row0 + i) * CC + kc + c];
        }
        // Load W tiles: 32x64 each (coalesced)
#pragma unroll
        for (int idx = tid; idx < PROJ_KC * HH; idx += 256) {
            int r = idx >> 6;
            int h = idx & 63;
            Ws_k[r][h] = Wk[(size_t)(kc + r) * HH + h];
            Ws_q[r][h] = Wq[(size_t)(kc + r) * HH + h];
            Ws_v[r][h] = Wv[(size_t)(kc + r) * HH + h];
        }
        __syncthreads();

#pragma unroll 8
        for (int c = 0; c < PROJ_KC; c++) {
            float xr[4], wk[4], wq[4], wv[4];
#pragma unroll
            for (int r = 0; r < 4; r++) xr[r] = Xs[ty * 4 + r][c];
#pragma unroll
            for (int j = 0; j < 4; j++) {
                wk[j] = Ws_k[c][tx * 4 + j];
                wq[j] = Ws_q[c][tx * 4 + j];
                wv[j] = Ws_v[c][tx * 4 + j];
            }
#pragma unroll
            for (int r = 0; r < 4; r++)
#pragma unroll
                for (int j = 0; j < 4; j++) {
                    ak[r][j] = fmaf(xr[r], wk[j], ak[r][j]);
                    aq[r][j] = fmaf(xr[r], wq[j], aq[r][j]);
                    av[r][j] = fmaf(xr[r], wv[j], av[r][j]);
                }
        }
        __syncthreads();
    }

#pragma unroll
    for (int r = 0; r < 4; r++) {
        size_t grow = (size_t)(row0 + ty * 4 + r);
#pragma unroll
        for (int j = 0; j < 4; j++) {
            int h = tx * 4 + j;
            g_k[grow * HH + h] = ak[r][j];
            g_q[grow * HH + h] = aq[r][j];
            g_v[grow * HH + h] = av[r][j];
        }
    }
}

// ---------------------------------------------------------------------------
// Kernel 2: flash attention (causal), fp32.
// Q tile = 64 rows, KV tile = 64 rows, head dim 64.
// One block handles the pair of q-tiles (p, 63-p) so every block does exactly
// 65 KV tiles -> balanced single wave of 128 blocks.
// Block: 256 threads (16x16). Each thread owns a 4(row) x 4(col) micro-tile
// of S/P and of O.
// ---------------------------------------------------------------------------
#define QTILE 64
#define KTILE 64
#define LD    65          // smem row pitch (+1 pad)
#define ATTN_SMEM (4 * 64 * LD * sizeof(float))   // Qs, Ks, Vs, Ps

__global__ __launch_bounds__(256) void attn_kernel(float* __restrict__ out)
{
    extern __shared__ float sm[];
    float* Qs = sm;
    float* Ks = sm + 1 * 64 * LD;
    float* Vs = sm + 2 * 64 * LD;
    float* Ps = sm + 3 * 64 * LD;

    const int tid = threadIdx.x;
    const int tx  = tid & 15;
    const int ty  = tid >> 4;
    const int b   = blockIdx.y;
    const int p   = blockIdx.x;          // 0..31
    const float scale = 0.03125f;        // C^-0.5 = 1024^-0.5 = 1/32

    for (int half = 0; half < 2; half++) {
        const int qt = (half == 0) ? p : (63 - p);
        const int qrow0 = qt * QTILE;

        // Load Q tile
#pragma unroll
        for (int idx = tid; idx < QTILE * HH; idx += 256) {
            int i = idx >> 6;
            int h = idx & 63;
            Qs[i * LD + h] = g_q[((size_t)b * TT + qrow0 + i) * HH + h];
        }
        __syncthreads();

        float m[4], l[4], O[4][4];
#pragma unroll
        for (int r = 0; r < 4; r++) {
            m[r] = -INFINITY; l[r] = 0.f;
#pragma unroll
            for (int c = 0; c < 4; c++) O[r][c] = 0.f;
        }

        const int nkt = qt + 1;
        for (int kt = 0; kt < nkt; kt++) {
            const int krow0 = kt * KTILE;
            // Load K,V tiles
#pragma unroll
            for (int idx = tid; idx < KTILE * HH; idx += 256) {
                int i = idx >> 6;
                int h = idx & 63;
                size_t g = ((size_t)b * TT + krow0 + i) * HH + h;
                Ks[i * LD + h] = g_k[g];
                Vs[i * LD + h] = g_v[g];
            }
            __syncthreads();

            // S = scale * Q K^T  (4x4 per thread)
            float S[4][4];
#pragma unroll
            for (int r = 0; r < 4; r++)
#pragma unroll
                for (int c = 0; c < 4; c++) S[r][c] = 0.f;

#pragma unroll 16
            for (int h = 0; h < HH; h++) {
                float qr[4], kr[4];
#pragma unroll
                for (int r = 0; r < 4; r++) qr[r] = Qs[(ty * 4 + r) * LD + h];
#pragma unroll
                for (int c = 0; c < 4; c++) kr[c] = Ks[(tx * 4 + c) * LD + h];
#pragma unroll
                for (int r = 0; r < 4; r++)
#pragma unroll
                    for (int c = 0; c < 4; c++)
                        S[r][c] = fmaf(qr[r], kr[c], S[r][c]);
            }

            const bool diag = (kt == qt);
#pragma unroll
            for (int r = 0; r < 4; r++) {
                int qi = qrow0 + ty * 4 + r;
#pragma unroll
                for (int c = 0; c < 4; c++) {
                    S[r][c] *= scale;
                    if (diag && (krow0 + tx * 4 + c > qi)) S[r][c] = -INFINITY;
                }
            }

            // Row max across the 16 tx lanes (lanes 0..15 within each half-warp)
            float mt[4];
#pragma unroll
            for (int r = 0; r < 4; r++) {
                float v = S[r][0];
#pragma unroll
                for (int c = 1; c < 4; c++) v = fmaxf(v, S[r][c]);
#pragma unroll
                for (int off = 8; off > 0; off >>= 1)
                    v = fmaxf(v, __shfl_xor_sync(0xffffffffu, v, off));
                mt[r] = v;
            }

            float mn[4], corr[4];
#pragma unroll
            for (int r = 0; r < 4; r++) {
                mn[r]   = fmaxf(m[r], mt[r]);
                corr[r] = __expf(m[r] - mn[r]);   // m=-inf -> 0
            }

            // P = exp(S - mn), row sums, stage P in smem
            float rs[4];
#pragma unroll
            for (int r = 0; r < 4; r++) {
                float s = 0.f;
#pragma unroll
                for (int c = 0; c < 4; c++) {
                    float pe = __expf(S[r][c] - mn[r]);
                    Ps[(ty * 4 + r) * LD + tx * 4 + c] = pe;
                    s += pe;
                }
#pragma unroll
                for (int off = 8; off > 0; off >>= 1)
                    s += __shfl_xor_sync(0xffffffffu, s, off);
                rs[r] = s;
            }

#pragma unroll
            for (int r = 0; r < 4; r++) {
                l[r] = l[r] * corr[r] + rs[r];
                m[r] = mn[r];
#pragma unroll
                for (int c = 0; c < 4; c++) O[r][c] *= corr[r];
            }
            __syncthreads();   // Ps visible to all

            // O += P @ V
#pragma unroll 16
            for (int j = 0; j < KTILE; j++) {
                float pr[4], vr[4];
#pragma unroll
                for (int r = 0; r < 4; r++) pr[r] = Ps[(ty * 4 + r) * LD + j];
#pragma unroll
                for (int c = 0; c < 4; c++) vr[c] = Vs[j * LD + tx * 4 + c];
#pragma unroll
                for (int r = 0; r < 4; r++)
#pragma unroll
                    for (int c = 0; c < 4; c++)
                        O[r][c] = fmaf(pr[r], vr[c], O[r][c]);
            }
            __syncthreads();   // before next tile overwrites Ks/Vs/Ps
        }

        // Write normalized output
#pragma unroll
        for (int r = 0; r < 4; r++) {
            float inv = 1.0f / l[r];
            size_t grow = (size_t)b * TT + qrow0 + ty * 4 + r;
#pragma unroll
            for (int c = 0; c < 4; c++)
                out[grow * HH + tx * 4 + c] = O[r][c] * inv;
        }
        __syncthreads();       // before next half reloads Qs
    }
}

// ---------------------------------------------------------------------------
extern "C" void kernel_launch(void* const* d_in, const int* in_sizes, int n_in,
                              void* d_out, int out_size)
{
    const float* x  = (const float*)d_in[0];
    const float* Wk = (const float*)d_in[1];
    const float* Wq = (const float*)d_in[2];
    const float* Wv = (const float*)d_in[3];
    float* out = (float*)d_out;

    proj_kernel<<<(BB * TT) / PROJ_ROWS, 256>>>(x, Wk, Wq, Wv);

    cudaFuncSetAttribute(attn_kernel,
                         cudaFuncAttributeMaxDynamicSharedMemorySize,
                         (int)ATTN_SMEM);
    attn_kernel<<<dim3(32, BB), 256, ATTN_SMEM>>>(out);
}

// round 4
// speedup vs baseline: 1.0487x; 1.0487x over previous
#include <cuda_runtime.h>
#include <math.h>
#include <stdint.h>

#define BB 4
#define TT 4096
#define CC 1024
#define HH 64

// Scratch for projected q,k,v  (12 MB total, __device__ globals per harness rules)
__device__ float g_q[(size_t)BB * TT * HH];
__device__ float g_k[(size_t)BB * TT * HH];
__device__ float g_v[(size_t)BB * TT * HH];

// ---------------------------------------------------------------------------
// Kernel 1: fused QKV projection.  x:[B*T, C] @ W{k,q,v}:[C, H] -> [B*T, H]
// Grid: 256 blocks x 64 rows. Block: 256 threads (16x16), 4x4 micro-tile,
// 3 accumulators per thread element (k,q,v share the x operand).
// ---------------------------------------------------------------------------
#define PROJ_ROWS 64
#define PROJ_KC   32

__global__ __launch_bounds__(256) void proj_kernel(
    const float* __restrict__ x,
    const float* __restrict__ Wk,
    const float* __restrict__ Wq,
    const float* __restrict__ Wv)
{
    __shared__ float Xs[PROJ_ROWS][PROJ_KC + 1];
    __shared__ float Ws_k[PROJ_KC][HH + 1];
    __shared__ float Ws_q[PROJ_KC][HH + 1];
    __shared__ float Ws_v[PROJ_KC][HH + 1];

    const int tid = threadIdx.x;
    const int tx  = tid & 15;
    const int ty  = tid >> 4;
    const int row0 = blockIdx.x * PROJ_ROWS;

    float ak[4][4], aq[4][4], av[4][4];
#pragma unroll
    for (int r = 0; r < 4; r++)
#pragma unroll
        for (int j = 0; j < 4; j++) { ak[r][j] = 0.f; aq[r][j] = 0.f; av[r][j] = 0.f; }

    for (int kc = 0; kc < CC; kc += PROJ_KC) {
        // Load X tile: 64x32 (coalesced)
#pragma unroll
        for (int idx = tid; idx < PROJ_ROWS * PROJ_KC; idx += 256) {
            int i = idx >> 5;
            int c = idx & 31;
            Xs[i][c] = x[(size_t)(row0 + i) * CC + kc + c];
        }
        // Load W tiles: 32x64 each (coalesced)
#pragma unroll
        for (int idx = tid; idx < PROJ_KC * HH; idx += 256) {
            int r = idx >> 6;
            int h = idx & 63;
            Ws_k[r][h] = Wk[(size_t)(kc + r) * HH + h];
            Ws_q[r][h] = Wq[(size_t)(kc + r) * HH + h];
            Ws_v[r][h] = Wv[(size_t)(kc + r) * HH + h];
        }
        __syncthreads();

#pragma unroll 8
        for (int c = 0; c < PROJ_KC; c++) {
            float xr[4], wk[4], wq[4], wv[4];
#pragma unroll
            for (int r = 0; r < 4; r++) xr[r] = Xs[ty * 4 + r][c];
#pragma unroll
            for (int j = 0; j < 4; j++) {
                wk[j] = Ws_k[c][tx * 4 + j];
                wq[j] = Ws_q[c][tx * 4 + j];
                wv[j] = Ws_v[c][tx * 4 + j];
            }
#pragma unroll
            for (int r = 0; r < 4; r++)
#pragma unroll
                for (int j = 0; j < 4; j++) {
                    ak[r][j] = fmaf(xr[r], wk[j], ak[r][j]);
                    aq[r][j] = fmaf(xr[r], wq[j], aq[r][j]);
                    av[r][j] = fmaf(xr[r], wv[j], av[r][j]);
                }
        }
        __syncthreads();
    }

#pragma unroll
    for (int r = 0; r < 4; r++) {
        size_t grow = (size_t)(row0 + ty * 4 + r);
#pragma unroll
        for (int j = 0; j < 4; j++) {
            int h = tx * 4 + j;
            g_k[grow * HH + h] = ak[r][j];
            g_q[grow * HH + h] = aq[r][j];
            g_v[grow * HH + h] = av[r][j];
        }
    }
}

// ---------------------------------------------------------------------------
// Kernel 2: flash attention (causal), fp32.
// Q tile = 64 rows, KV tile = 64 rows, head dim 64.
// One block handles the pair of q-tiles (p, 63-p) so every block does exactly
// 65 KV tiles -> balanced single wave of 128 blocks.
// Block: 256 threads (16x16). Each thread owns a 4(row) x 4(col) micro-tile
// of S/P and of O.
// ---------------------------------------------------------------------------
#define QTILE 64
#define KTILE 64
#define LD    65          // smem row pitch (+1 pad)
#define ATTN_SMEM (4 * 64 * LD * sizeof(float))   // Qs, Ks, Vs, Ps

__global__ __launch_bounds__(256) void attn_kernel(float* __restrict__ out)
{
    extern __shared__ float sm[];
    float* Qs = sm;
    float* Ks = sm + 1 * 64 * LD;
    float* Vs = sm + 2 * 64 * LD;
    float* Ps = sm + 3 * 64 * LD;

    const int tid = threadIdx.x;
    const int tx  = tid & 15;
    const int ty  = tid >> 4;
    const int b   = blockIdx.y;
    const int p   = blockIdx.x;          // 0..31
    const float scale = 0.03125f;        // C^-0.5 = 1024^-0.5 = 1/32

    for (int half = 0; half < 2; half++) {
        const int qt = (half == 0) ? p : (63 - p);
        const int qrow0 = qt * QTILE;

        // Load Q tile
#pragma unroll
        for (int idx = tid; idx < QTILE * HH; idx += 256) {
            int i = idx >> 6;
            int h = idx & 63;
            Qs[i * LD + h] = g_q[((size_t)b * TT + qrow0 + i) * HH + h];
        }
        __syncthreads();

        float m[4], l[4], O[4][4];
#pragma unroll
        for (int r = 0; r < 4; r++) {
            m[r] = -INFINITY; l[r] = 0.f;
#pragma unroll
            for (int c = 0; c < 4; c++) O[r][c] = 0.f;
        }

        const int nkt = qt + 1;
        for (int kt = 0; kt < nkt; kt++) {
            const int krow0 = kt * KTILE;
            // Load K,V tiles
#pragma unroll
            for (int idx = tid; idx < KTILE * HH; idx += 256) {
                int i = idx >> 6;
                int h = idx & 63;
                size_t g = ((size_t)b * TT + krow0 + i) * HH + h;
                Ks[i * LD + h] = g_k[g];
                Vs[i * LD + h] = g_v[g];
            }
            __syncthreads();

            // S = scale * Q K^T  (4x4 per thread)
            float S[4][4];
#pragma unroll
            for (int r = 0; r < 4; r++)
#pragma unroll
                for (int c = 0; c < 4; c++) S[r][c] = 0.f;

#pragma unroll 16
            for (int h = 0; h < HH; h++) {
                float qr[4], kr[4];
#pragma unroll
                for (int r = 0; r < 4; r++) qr[r] = Qs[(ty * 4 + r) * LD + h];
#pragma unroll
                for (int c = 0; c < 4; c++) kr[c] = Ks[(tx * 4 + c) * LD + h];
#pragma unroll
                for (int r = 0; r < 4; r++)
#pragma unroll
                    for (int c = 0; c < 4; c++)
                        S[r][c] = fmaf(qr[r], kr[c], S[r][c]);
            }

            const bool diag = (kt == qt);
#pragma unroll
            for (int r = 0; r < 4; r++) {
                int qi = qrow0 + ty * 4 + r;
#pragma unroll
                for (int c = 0; c < 4; c++) {
                    S[r][c] *= scale;
                    if (diag && (krow0 + tx * 4 + c > qi)) S[r][c] = -INFINITY;
                }
            }

            // Row max across the 16 tx lanes (lanes 0..15 within each half-warp)
            float mt[4];
#pragma unroll
            for (int r = 0; r < 4; r++) {
                float v = S[r][0];
#pragma unroll
                for (int c = 1; c < 4; c++) v = fmaxf(v, S[r][c]);
#pragma unroll
                for (int off = 8; off > 0; off >>= 1)
                    v = fmaxf(v, __shfl_xor_sync(0xffffffffu, v, off));
                mt[r] = v;
            }

            float mn[4], corr[4];
#pragma unroll
            for (int r = 0; r < 4; r++) {
                mn[r]   = fmaxf(m[r], mt[r]);
                corr[r] = __expf(m[r] - mn[r]);   // m=-inf -> 0
            }

            // P = exp(S - mn), row sums, stage P in smem
            float rs[4];
#pragma unroll
            for (int r = 0; r < 4; r++) {
                float s = 0.f;
#pragma unroll
                for (int c = 0; c < 4; c++) {
                    float pe = __expf(S[r][c] - mn[r]);
                    Ps[(ty * 4 + r) * LD + tx * 4 + c] = pe;
                    s += pe;
                }
#pragma unroll
                for (int off = 8; off > 0; off >>= 1)
                    s += __shfl_xor_sync(0xffffffffu, s, off);
                rs[r] = s;
            }

#pragma unroll
            for (int r = 0; r < 4; r++) {
                l[r] = l[r] * corr[r] + rs[r];
                m[r] = mn[r];
#pragma unroll
                for (int c = 0; c < 4; c++) O[r][c] *= corr[r];
            }
            __syncthreads();   // Ps visible to all

            // O += P @ V
#pragma unroll 16
            for (int j = 0; j < KTILE; j++) {
                float pr[4], vr[4];
#pragma unroll
                for (int r = 0; r < 4; r++) pr[r] = Ps[(ty * 4 + r) * LD + j];
#pragma unroll
                for (int c = 0; c < 4; c++) vr[c] = Vs[j * LD + tx * 4 + c];
#pragma unroll
                for (int r = 0; r < 4; r++)
#pragma unroll
                    for (int c = 0; c < 4; c++)
                        O[r][c] = fmaf(pr[r], vr[c], O[r][c]);
            }
            __syncthreads();   // before next tile overwrites Ks/Vs/Ps
        }

        // Write normalized output
#pragma unroll
        for (int r = 0; r < 4; r++) {
            float inv = 1.0f / l[r];
            size_t grow = (size_t)b * TT + qrow0 + ty * 4 + r;
#pragma unroll
            for (int c = 0; c < 4; c++)
                out[grow * HH + tx * 4 + c] = O[r][c] * inv;
        }
        __syncthreads();       // before next half reloads Qs
    }
}

// ---------------------------------------------------------------------------
extern "C" void kernel_launch(void* const* d_in, const int* in_sizes, int n_in,
                              void* d_out, int out_size)
{
    const float* x  = (const float*)d_in[0];
    const float* Wk = (const float*)d_in[1];
    const float* Wq = (const float*)d_in[2];
    const float* Wv = (const float*)d_in[3];
    float* out = (float*)d_out;

    proj_kernel<<<(BB * TT) / PROJ_ROWS, 256>>>(x, Wk, Wq, Wv);

    cudaFuncSetAttribute(attn_kernel,
                         cudaFuncAttributeMaxDynamicSharedMemorySize,
                         (int)ATTN_SMEM);
    attn_kernel<<<dim3(32, BB), 256, ATTN_SMEM>>>(out);
}

// round 5
// speedup vs baseline: 1.0494x; 1.0007x over previous
#include <cuda_runtime.h>
#include <math.h>
#include <stdint.h>

#define BB 4
#define TT 4096
#define CC 1024
#define HH 64

// Scratch for projected q,k,v (12 MB, __device__ globals per harness rules)
__device__ float g_q[(size_t)BB * TT * HH];
__device__ float g_k[(size_t)BB * TT * HH];
__device__ float g_v[(size_t)BB * TT * HH];

// ---------------------------------------------------------------------------
// Kernel 1: fused QKV projection.  x:[B*T, C] @ W{k,q,v}:[C, H] -> [B*T, H]
// 256 blocks x 64 rows, 256 threads (16x16), 4x4 micro-tile, vectorized LDS.
// ---------------------------------------------------------------------------
#define PROJ_ROWS 64
#define PROJ_KC   32
#define XPIT      68     // pitch for transposed X tile (mult of 4, odd bank step)

__global__ __launch_bounds__(256) void proj_kernel(
    const float* __restrict__ x,
    const float* __restrict__ Wk,
    const float* __restrict__ Wq,
    const float* __restrict__ Wv)
{
    __shared__ float Xt[PROJ_KC][XPIT];        // [c][row]  (transposed)
    __shared__ float Wks[PROJ_KC][HH];
    __shared__ float Wqs[PROJ_KC][HH];
    __shared__ float Wvs[PROJ_KC][HH];

    const int tid = threadIdx.x;
    const int tx  = tid & 15;
    const int ty  = tid >> 4;
    const int row0 = blockIdx.x * PROJ_ROWS;

    float ak[4][4], aq[4][4], av[4][4];
#pragma unroll
    for (int r = 0; r < 4; r++)
#pragma unroll
        for (int j = 0; j < 4; j++) { ak[r][j] = 0.f; aq[r][j] = 0.f; av[r][j] = 0.f; }

    for (int kc = 0; kc < CC; kc += PROJ_KC) {
        // X tile: 64 rows x 32 cols, float4 gmem loads, transposed scatter to smem
#pragma unroll
        for (int idx = tid; idx < PROJ_ROWS * (PROJ_KC / 4); idx += 256) {
            int i  = idx >> 3;
            int cb = (idx & 7) * 4;
            float4 xv = *(const float4*)(x + (size_t)(row0 + i) * CC + kc + cb);
            Xt[cb + 0][i] = xv.x;
            Xt[cb + 1][i] = xv.y;
            Xt[cb + 2][i] = xv.z;
            Xt[cb + 3][i] = xv.w;
        }
        // W tiles: 32 x 64 each, float4 in and out
#pragma unroll
        for (int idx = tid; idx < PROJ_KC * (HH / 4); idx += 256) {
            int r  = idx >> 4;
            int hb = (idx & 15) * 4;
            size_t g = (size_t)(kc + r) * HH + hb;
            *(float4*)(&Wks[r][hb]) = *(const float4*)(Wk + g);
            *(float4*)(&Wqs[r][hb]) = *(const float4*)(Wq + g);
            *(float4*)(&Wvs[r][hb]) = *(const float4*)(Wv + g);
        }
        __syncthreads();

#pragma unroll 4
        for (int c = 0; c < PROJ_KC; c++) {
            float4 x4 = *(const float4*)(&Xt[c][ty * 4]);
            float4 k4 = *(const float4*)(&Wks[c][tx * 4]);
            float4 q4 = *(const float4*)(&Wqs[c][tx * 4]);
            float4 v4 = *(const float4*)(&Wvs[c][tx * 4]);
            float xr[4] = {x4.x, x4.y, x4.z, x4.w};
            float wk[4] = {k4.x, k4.y, k4.z, k4.w};
            float wq[4] = {q4.x, q4.y, q4.z, q4.w};
            float wv[4] = {v4.x, v4.y, v4.z, v4.w};
#pragma unroll
            for (int r = 0; r < 4; r++)
#pragma unroll
                for (int j = 0; j < 4; j++) {
                    ak[r][j] = fmaf(xr[r], wk[j], ak[r][j]);
                    aq[r][j] = fmaf(xr[r], wq[j], aq[r][j]);
                    av[r][j] = fmaf(xr[r], wv[j], av[r][j]);
                }
        }
        __syncthreads();
    }

#pragma unroll
    for (int r = 0; r < 4; r++) {
        size_t grow = (size_t)(row0 + ty * 4 + r) * HH + tx * 4;
        *(float4*)(g_k + grow) = make_float4(ak[r][0], ak[r][1], ak[r][2], ak[r][3]);
        *(float4*)(g_q + grow) = make_float4(aq[r][0], aq[r][1], aq[r][2], aq[r][3]);
        *(float4*)(g_v + grow) = make_float4(av[r][0], av[r][1], av[r][2], av[r][3]);
    }
}

// ---------------------------------------------------------------------------
// Kernel 2: flash attention (causal), fp32, vectorized LDS.
// One 512-thread block = two independent 256-thread groups handling the
// balanced q-tile pair (p, 63-p): every block does exactly 65 KV tiles.
// Groups sync with named barriers (they run different trip counts).
// Smem layouts (pitch 68): Qt[h][row], Kt[h][col], Vs[j][col], Ps[row][col].
// ---------------------------------------------------------------------------
#define PIT 68
#define GRP_SMEM (4 * 64 * PIT)                       // floats per group
#define ATTN_SMEM (2 * GRP_SMEM * sizeof(float))      // 139264 bytes

__device__ __forceinline__ void group_bar(int id) {
    asm volatile("bar.sync %0, %1;" :: "r"(id), "r"(256) : "memory");
}

__global__ __launch_bounds__(512, 1) void attn_kernel(float* __restrict__ out)
{
    extern __shared__ float sm[];
    const int tid  = threadIdx.x;
    const int grp  = tid >> 8;           // 0 or 1
    const int gtid = tid & 255;
    const int tx   = gtid & 15;
    const int ty   = gtid >> 4;
    const int bar  = grp + 1;            // named barrier id (0 = default)

    float* base = sm + grp * GRP_SMEM;
    float* Qt = base;                    // [h][row]
    float* Kt = base + 1 * 64 * PIT;     // [h][col]
    float* Vs = base + 2 * 64 * PIT;     // [j][col]
    float* Ps = base + 3 * 64 * PIT;     // [row][col]

    const int b  = blockIdx.y;
    const int p  = blockIdx.x;           // 0..31
    const int qt = (grp == 0) ? p : (63 - p);
    const int qrow0 = qt * 64;
    const float scale = 0.03125f;        // 1024^-0.5

    // Load Q (scaled), transposed: float4 gmem read, scalar scatter
#pragma unroll
    for (int idx = gtid; idx < 64 * 16; idx += 256) {
        int i  = idx >> 4;
        int hb = (idx & 15) * 4;
        float4 qv = *(const float4*)(g_q + ((size_t)b * TT + qrow0 + i) * HH + hb);
        Qt[(hb + 0) * PIT + i] = qv.x * scale;
        Qt[(hb + 1) * PIT + i] = qv.y * scale;
        Qt[(hb + 2) * PIT + i] = qv.z * scale;
        Qt[(hb + 3) * PIT + i] = qv.w * scale;
    }
    group_bar(bar);

    float m[4], l[4], O[4][4];
#pragma unroll
    for (int r = 0; r < 4; r++) {
        m[r] = -INFINITY; l[r] = 0.f;
#pragma unroll
        for (int c = 0; c < 4; c++) O[r][c] = 0.f;
    }

    const int nkt = qt + 1;
    for (int kt = 0; kt < nkt; kt++) {
        const int krow0 = kt * 64;
        // Load K (transposed) and V (row-major), float4 gmem reads
#pragma unroll
        for (int idx = gtid; idx < 64 * 16; idx += 256) {
            int i  = idx >> 4;
            int hb = (idx & 15) * 4;
            size_t g = ((size_t)b * TT + krow0 + i) * HH + hb;
            float4 kv = *(const float4*)(g_k + g);
            Kt[(hb + 0) * PIT + i] = kv.x;
            Kt[(hb + 1) * PIT + i] = kv.y;
            Kt[(hb + 2) * PIT + i] = kv.z;
            Kt[(hb + 3) * PIT + i] = kv.w;
            *(float4*)(Vs + i * PIT + hb) = *(const float4*)(g_v + g);
        }
        group_bar(bar);

        // S = (scaled Q) K^T, 4x4 per thread, float4 LDS
        float S[4][4];
#pragma unroll
        for (int r = 0; r < 4; r++)
#pragma unroll
            for (int c = 0; c < 4; c++) S[r][c] = 0.f;

#pragma unroll 4
        for (int h = 0; h < HH; h++) {
            float4 q4 = *(const float4*)(Qt + h * PIT + 4 * ty);
            float4 k4 = *(const float4*)(Kt + h * PIT + 4 * tx);
            float qr[4] = {q4.x, q4.y, q4.z, q4.w};
            float kr[4] = {k4.x, k4.y, k4.z, k4.w};
#pragma unroll
            for (int r = 0; r < 4; r++)
#pragma unroll
                for (int c = 0; c < 4; c++)
                    S[r][c] = fmaf(qr[r], kr[c], S[r][c]);
        }

        const bool diag = (kt == qt);
        if (diag) {
#pragma unroll
            for (int r = 0; r < 4; r++) {
                int qi = qrow0 + ty * 4 + r;
#pragma unroll
                for (int c = 0; c < 4; c++)
                    if (krow0 + tx * 4 + c > qi) S[r][c] = -INFINITY;
            }
        }

        // Row max across 16 tx lanes
        float mt[4];
#pragma unroll
        for (int r = 0; r < 4; r++) {
            float v = fmaxf(fmaxf(S[r][0], S[r][1]), fmaxf(S[r][2], S[r][3]));
#pragma unroll
            for (int off = 8; off > 0; off >>= 1)
                v = fmaxf(v, __shfl_xor_sync(0xffffffffu, v, off));
            mt[r] = v;
        }

        float mn[4], corr[4];
#pragma unroll
        for (int r = 0; r < 4; r++) {
            mn[r]   = fmaxf(m[r], mt[r]);
            corr[r] = __expf(m[r] - mn[r]);          // m=-inf -> 0
        }

        // P = exp(S - mn): float4 store, row-sum via shuffles
        float rs[4];
#pragma unroll
        for (int r = 0; r < 4; r++) {
            float p0 = __expf(S[r][0] - mn[r]);
            float p1 = __expf(S[r][1] - mn[r]);
            float p2 = __expf(S[r][2] - mn[r]);
            float p3 = __expf(S[r][3] - mn[r]);
            *(float4*)(Ps + (ty * 4 + r) * PIT + tx * 4) = make_float4(p0, p1, p2, p3);
            float s = (p0 + p1) + (p2 + p3);
#pragma unroll
            for (int off = 8; off > 0; off >>= 1)
                s += __shfl_xor_sync(0xffffffffu, s, off);
            rs[r] = s;
        }

#pragma unroll
        for (int r = 0; r < 4; r++) {
            l[r] = l[r] * corr[r] + rs[r];
            m[r] = mn[r];
#pragma unroll
            for (int c = 0; c < 4; c++) O[r][c] *= corr[r];
        }
        group_bar(bar);   // Ps/Vs ready for all threads in group

        // O += P @ V : unroll j by 4, all-float4 LDS
#pragma unroll 2
        for (int j = 0; j < 64; j += 4) {
            float4 pr4[4], vr4[4];
#pragma unroll
            for (int r = 0; r < 4; r++)
                pr4[r] = *(const float4*)(Ps + (ty * 4 + r) * PIT + j);
#pragma unroll
            for (int jj = 0; jj < 4; jj++)
                vr4[jj] = *(const float4*)(Vs + (j + jj) * PIT + tx * 4);
#pragma unroll
            for (int r = 0; r < 4; r++) {
                float pj[4] = {pr4[r].x, pr4[r].y, pr4[r].z, pr4[r].w};
#pragma unroll
                for (int jj = 0; jj < 4; jj++) {
                    O[r][0] = fmaf(pj[jj], vr4[jj].x, O[r][0]);
                    O[r][1] = fmaf(pj[jj], vr4[jj].y, O[r][1]);
                    O[r][2] = fmaf(pj[jj], vr4[jj].z, O[r][2]);
                    O[r][3] = fmaf(pj[jj], vr4[jj].w, O[r][3]);
                }
            }
        }
        group_bar(bar);   // before next tile overwrites Kt/Vs/Ps
    }

    // Normalized output, float4 stores
#pragma unroll
    for (int r = 0; r < 4; r++) {
        float inv = 1.0f / l[r];
        size_t grow = ((size_t)b * TT + qrow0 + ty * 4 + r) * HH + tx * 4;
        *(float4*)(out + grow) =
            make_float4(O[r][0] * inv, O[r][1] * inv, O[r][2] * inv, O[r][3] * inv);
    }
}

// ---------------------------------------------------------------------------
extern "C" void kernel_launch(void* const* d_in, const int* in_sizes, int n_in,
                              void* d_out, int out_size)
{
    const float* x  = (const float*)d_in[0];
    const float* Wk = (const float*)d_in[1];
    const float* Wq = (const float*)d_in[2];
    const float* Wv = (const float*)d_in[3];
    float* out = (float*)d_out;

    proj_kernel<<<(BB * TT) / PROJ_ROWS, 256>>>(x, Wk, Wq, Wv);

    cudaFuncSetAttribute(attn_kernel,
                         cudaFuncAttributeMaxDynamicSharedMemorySize,
                         (int)ATTN_SMEM);
    attn_kernel<<<dim3(32, BB), 512, ATTN_SMEM>>>(out);
}

// round 6
// speedup vs baseline: 3.0216x; 2.8793x over previous
#include <cuda_runtime.h>
#include <math.h>
#include <stdint.h>

#define BB 4
#define TT 4096
#define CC 1024
#define HH 64

// Scratch for projected q,k,v (12 MB, __device__ globals per harness rules)
__device__ float g_q[(size_t)BB * TT * HH];
__device__ float g_k[(size_t)BB * TT * HH];
__device__ float g_v[(size_t)BB * TT * HH];

// ---------------------------------------------------------------------------
// tf32 helpers
// ---------------------------------------------------------------------------
__device__ __forceinline__ uint32_t f2tf(float f) {
    uint32_t u;
    asm("cvt.rna.tf32.f32 %0, %1;" : "=r"(u) : "f"(f));
    return u;
}

// D = A(16x8, row) * B(8x8, col) + D, tf32 in, f32 accum.
__device__ __forceinline__ void mma8(float* c,
                                     uint32_t a0, uint32_t a1, uint32_t a2, uint32_t a3,
                                     uint32_t b0, uint32_t b1) {
    asm volatile(
        "mma.sync.aligned.m16n8k8.row.col.f32.tf32.tf32.f32 "
        "{%0,%1,%2,%3}, {%4,%5,%6,%7}, {%8,%9}, {%0,%1,%2,%3};"
        : "+f"(c[0]), "+f"(c[1]), "+f"(c[2]), "+f"(c[3])
        : "r"(a0), "r"(a1), "r"(a2), "r"(a3), "r"(b0), "r"(b1));
}

// ---------------------------------------------------------------------------
// Kernel 1: fused QKV projection with tf32 mma.
// Block: 256 thr = 8 warps, tile M=128, N=64 (x3 matrices), K-chunks of 32.
// Warp = (wm: m32 slice) x (wn: n32 slice); B-fragments reused across 2 m-tiles.
// Smem pitches: Xs pitch 36 (row-indexed, banks 4g+t), Ws pitch 72 (k-indexed,
// banks 8t+g) -> all fragment LDS conflict-free.
// ---------------------------------------------------------------------------
#define PM  128
#define PKC 32
#define XP  36
#define WP  72

__global__ __launch_bounds__(256) void proj_kernel(
    const float* __restrict__ x,
    const float* __restrict__ Wk,
    const float* __restrict__ Wq,
    const float* __restrict__ Wv)
{
    __shared__ uint32_t Xs[PM * XP];          // 18432 B
    __shared__ uint32_t Ws[3][PKC * WP];      // 27648 B  (total 45 KB static)

    const int tid  = threadIdx.x;
    const int lane = tid & 31;
    const int wid  = tid >> 5;
    const int wm   = wid & 3;                 // m32 slice: rows wm*32
    const int wn   = wid >> 2;                // n32 slice: cols wn*32
    const int g    = lane >> 2;
    const int t    = lane & 3;
    const int row0 = blockIdx.x * PM;
    const float* W[3] = {Wk, Wq, Wv};

    float acc[3][2][4][4];
#pragma unroll
    for (int m = 0; m < 3; m++)
#pragma unroll
        for (int mt = 0; mt < 2; mt++)
#pragma unroll
            for (int nt = 0; nt < 4; nt++)
#pragma unroll
                for (int e = 0; e < 4; e++) acc[m][mt][nt][e] = 0.f;

    for (int kc = 0; kc < CC; kc += PKC) {
        // X tile: 128 x 32, coalesced float4, convert to tf32
#pragma unroll
        for (int idx = tid; idx < PM * (PKC / 4); idx += 256) {
            int i  = idx >> 3;
            int cb = (idx & 7) * 4;
            float4 xv = *(const float4*)(x + (size_t)(row0 + i) * CC + kc + cb);
            Xs[i * XP + cb + 0] = f2tf(xv.x);
            Xs[i * XP + cb + 1] = f2tf(xv.y);
            Xs[i * XP + cb + 2] = f2tf(xv.z);
            Xs[i * XP + cb + 3] = f2tf(xv.w);
        }
        // W tiles: 32 x 64 each
#pragma unroll
        for (int idx = tid; idx < PKC * (HH / 4); idx += 256) {
            int r  = idx >> 4;
            int hb = (idx & 15) * 4;
            size_t go = (size_t)(kc + r) * HH + hb;
#pragma unroll
            for (int m = 0; m < 3; m++) {
                float4 wv = *(const float4*)(W[m] + go);
                Ws[m][r * WP + hb + 0] = f2tf(wv.x);
                Ws[m][r * WP + hb + 1] = f2tf(wv.y);
                Ws[m][r * WP + hb + 2] = f2tf(wv.z);
                Ws[m][r * WP + hb + 3] = f2tf(wv.w);
            }
        }
        __syncthreads();

#pragma unroll
        for (int ks = 0; ks < 4; ks++) {
            const int k0 = ks * 8;
            uint32_t a[2][4];
#pragma unroll
            for (int mt = 0; mt < 2; mt++) {
                int ar = wm * 32 + mt * 16 + g;
                a[mt][0] = Xs[ar * XP + k0 + t];
                a[mt][1] = Xs[(ar + 8) * XP + k0 + t];
                a[mt][2] = Xs[ar * XP + k0 + t + 4];
                a[mt][3] = Xs[(ar + 8) * XP + k0 + t + 4];
            }
#pragma unroll
            for (int m = 0; m < 3; m++)
#pragma unroll
                for (int nt = 0; nt < 4; nt++) {
                    int n0 = wn * 32 + nt * 8;
                    uint32_t b0 = Ws[m][(k0 + t) * WP + n0 + g];
                    uint32_t b1 = Ws[m][(k0 + t + 4) * WP + n0 + g];
                    mma8(acc[m][0][nt], a[0][0], a[0][1], a[0][2], a[0][3], b0, b1);
                    mma8(acc[m][1][nt], a[1][0], a[1][1], a[1][2], a[1][3], b0, b1);
                }
        }
        __syncthreads();
    }

    float* G[3] = {g_k, g_q, g_v};
#pragma unroll
    for (int m = 0; m < 3; m++)
#pragma unroll
        for (int mt = 0; mt < 2; mt++) {
            int r0 = row0 + wm * 32 + mt * 16 + g;
#pragma unroll
            for (int nt = 0; nt < 4; nt++) {
                int c0 = wn * 32 + nt * 8 + 2 * t;
                float* dst = G[m] + (size_t)r0 * HH + c0;
                *(float2*)dst = make_float2(acc[m][mt][nt][0], acc[m][mt][nt][1]);
                *(float2*)(dst + (size_t)8 * HH) =
                    make_float2(acc[m][mt][nt][2], acc[m][mt][nt][3]);
            }
        }
}

// ---------------------------------------------------------------------------
// Kernel 2: causal flash attention with tf32 mma.
// Block: 256 thr = 2 groups x 4 warps. Group grp handles q-tile (p / 63-p)
// => every block does exactly 65 KV tiles (balanced single wave of 128 blocks).
// Warp = one m16 slice, full N=64 (8 n8-tiles) -> softmax reductions stay
// inside a lane quad. Groups sync with named barriers (128 threads each).
// Smem per group (tf32): Qs[64x68], Ks[64x68], Vs[64x72], Ps[64x68].
// ---------------------------------------------------------------------------
#define QP 68
#define VP 72
#define GRP_U32 (64 * QP * 3 + 64 * VP)          // 17664 u32 per group
#define ATTN_SMEM (2 * GRP_U32 * 4)              // 141312 bytes

__device__ __forceinline__ void group_bar(int id) {
    asm volatile("bar.sync %0, %1;" :: "r"(id), "r"(128) : "memory");
}

__global__ __launch_bounds__(256, 1) void attn_kernel(float* __restrict__ out)
{
    extern __shared__ uint32_t sm[];
    const int tid  = threadIdx.x;
    const int lane = tid & 31;
    const int wid  = tid >> 5;
    const int grp  = wid >> 2;              // 0 or 1
    const int lw   = wid & 3;               // m16 slice within group
    const int gtid = tid & 127;
    const int g    = lane >> 2;
    const int t    = lane & 3;
    const int bar  = grp + 1;

    uint32_t* base = sm + grp * GRP_U32;
    uint32_t* Qs = base;
    uint32_t* Ks = base + 64 * QP;
    uint32_t* Vs = base + 2 * 64 * QP;
    uint32_t* Ps = base + 2 * 64 * QP + 64 * VP;

    const int b  = blockIdx.y;
    const int p  = blockIdx.x;              // 0..31
    const int qt = grp ? (63 - p) : p;
    const int qrow0 = qt * 64;
    const float scale = 0.03125f;           // 1024^-0.5

    // Load Q (pre-scaled, tf32)
#pragma unroll
    for (int idx = gtid; idx < 64 * 16; idx += 128) {
        int i  = idx >> 4;
        int hb = (idx & 15) * 4;
        float4 qv = *(const float4*)(g_q + ((size_t)b * TT + qrow0 + i) * HH + hb);
        Qs[i * QP + hb + 0] = f2tf(qv.x * scale);
        Qs[i * QP + hb + 1] = f2tf(qv.y * scale);
        Qs[i * QP + hb + 2] = f2tf(qv.z * scale);
        Qs[i * QP + hb + 3] = f2tf(qv.w * scale);
    }

    float m0v = -INFINITY, m1v = -INFINITY, l0 = 0.f, l1 = 0.f;
    float O[8][4];
#pragma unroll
    for (int nt = 0; nt < 8; nt++)
#pragma unroll
        for (int e = 0; e < 4; e++) O[nt][e] = 0.f;

    const int arow = lw * 16 + g;

    for (int kt = 0; kt <= qt; kt++) {
        const int krow0 = kt * 64;
        // Load K, V tiles (tf32)
#pragma unroll
        for (int idx = gtid; idx < 64 * 16; idx += 128) {
            int i  = idx >> 4;
            int hb = (idx & 15) * 4;
            size_t go = ((size_t)b * TT + krow0 + i) * HH + hb;
            float4 kv = *(const float4*)(g_k + go);
            float4 vv = *(const float4*)(g_v + go);
            Ks[i * QP + hb + 0] = f2tf(kv.x);
            Ks[i * QP + hb + 1] = f2tf(kv.y);
            Ks[i * QP + hb + 2] = f2tf(kv.z);
            Ks[i * QP + hb + 3] = f2tf(kv.w);
            Vs[i * VP + hb + 0] = f2tf(vv.x);
            Vs[i * VP + hb + 1] = f2tf(vv.y);
            Vs[i * VP + hb + 2] = f2tf(vv.z);
            Vs[i * VP + hb + 3] = f2tf(vv.w);
        }
        group_bar(bar);   // also covers initial Q load on kt==0

        // S = Qs * Ks^T  (A row-major from Qs, B col-major from Ks rows)
        float S[8][4];
#pragma unroll
        for (int nt = 0; nt < 8; nt++)
#pragma unroll
            for (int e = 0; e < 4; e++) S[nt][e] = 0.f;

#pragma unroll
        for (int ks = 0; ks < 8; ks++) {
            const int k0 = ks * 8;
            uint32_t a0 = Qs[arow * QP + k0 + t];
            uint32_t a1 = Qs[(arow + 8) * QP + k0 + t];
            uint32_t a2 = Qs[arow * QP + k0 + t + 4];
            uint32_t a3 = Qs[(arow + 8) * QP + k0 + t + 4];
#pragma unroll
            for (int nt = 0; nt < 8; nt++) {
                uint32_t b0 = Ks[(nt * 8 + g) * QP + k0 + t];
                uint32_t b1 = Ks[(nt * 8 + g) * QP + k0 + t + 4];
                mma8(S[nt], a0, a1, a2, a3, b0, b1);
            }
        }

        // Causal mask (diagonal tile only)
        if (kt == qt) {
            int r0 = qrow0 + arow, r1 = r0 + 8;
#pragma unroll
            for (int nt = 0; nt < 8; nt++) {
                int c = krow0 + nt * 8 + 2 * t;
                if (c     > r0) S[nt][0] = -INFINITY;
                if (c + 1 > r0) S[nt][1] = -INFINITY;
                if (c     > r1) S[nt][2] = -INFINITY;
                if (c + 1 > r1) S[nt][3] = -INFINITY;
            }
        }

        // Row max (2 rows per thread, reduce over lane quad)
        float mt0 = -INFINITY, mt1 = -INFINITY;
#pragma unroll
        for (int nt = 0; nt < 8; nt++) {
            mt0 = fmaxf(mt0, fmaxf(S[nt][0], S[nt][1]));
            mt1 = fmaxf(mt1, fmaxf(S[nt][2], S[nt][3]));
        }
        mt0 = fmaxf(mt0, __shfl_xor_sync(0xffffffffu, mt0, 1));
        mt0 = fmaxf(mt0, __shfl_xor_sync(0xffffffffu, mt0, 2));
        mt1 = fmaxf(mt1, __shfl_xor_sync(0xffffffffu, mt1, 1));
        mt1 = fmaxf(mt1, __shfl_xor_sync(0xffffffffu, mt1, 2));

        float mn0 = fmaxf(m0v, mt0), mn1 = fmaxf(m1v, mt1);
        float cr0 = __expf(m0v - mn0), cr1 = __expf(m1v - mn1);

        // P = exp(S - mn), stage to Ps (tf32), row sums
        float rs0 = 0.f, rs1 = 0.f;
#pragma unroll
        for (int nt = 0; nt < 8; nt++) {
            float p0 = __expf(S[nt][0] - mn0);
            float p1 = __expf(S[nt][1] - mn0);
            float p2 = __expf(S[nt][2] - mn1);
            float p3 = __expf(S[nt][3] - mn1);
            rs0 += p0 + p1;
            rs1 += p2 + p3;
            uint2 u01; u01.x = f2tf(p0); u01.y = f2tf(p1);
            uint2 u23; u23.x = f2tf(p2); u23.y = f2tf(p3);
            *(uint2*)&Ps[arow * QP + nt * 8 + 2 * t]       = u01;
            *(uint2*)&Ps[(arow + 8) * QP + nt * 8 + 2 * t] = u23;
        }
        rs0 += __shfl_xor_sync(0xffffffffu, rs0, 1);
        rs0 += __shfl_xor_sync(0xffffffffu, rs0, 2);
        rs1 += __shfl_xor_sync(0xffffffffu, rs1, 1);
        rs1 += __shfl_xor_sync(0xffffffffu, rs1, 2);

        l0 = l0 * cr0 + rs0;
        l1 = l1 * cr1 + rs1;
        m0v = mn0; m1v = mn1;
#pragma unroll
        for (int nt = 0; nt < 8; nt++) {
            O[nt][0] *= cr0; O[nt][1] *= cr0;
            O[nt][2] *= cr1; O[nt][3] *= cr1;
        }
        group_bar(bar);   // Ps complete for whole group

        // O += Ps * Vs   (A row-major from Ps, B col-major from Vs rows)
#pragma unroll
        for (int ks = 0; ks < 8; ks++) {
            const int k0 = ks * 8;
            uint32_t a0 = Ps[arow * QP + k0 + t];
            uint32_t a1 = Ps[(arow + 8) * QP + k0 + t];
            uint32_t a2 = Ps[arow * QP + k0 + t + 4];
            uint32_t a3 = Ps[(arow + 8) * QP + k0 + t + 4];
#pragma unroll
            for (int nt = 0; nt < 8; nt++) {
                uint32_t b0 = Vs[(k0 + t) * VP + nt * 8 + g];
                uint32_t b1 = Vs[(k0 + t + 4) * VP + nt * 8 + g];
                mma8(O[nt], a0, a1, a2, a3, b0, b1);
            }
        }
        group_bar(bar);   // before next tile overwrites Ks/Vs/Ps
    }

    // Normalize and write
    float i0 = 1.0f / l0, i1 = 1.0f / l1;
    const int r0 = qrow0 + arow;
#pragma unroll
    for (int nt = 0; nt < 8; nt++) {
        size_t o0 = ((size_t)b * TT + r0) * HH + nt * 8 + 2 * t;
        *(float2*)(out + o0)               = make_float2(O[nt][0] * i0, O[nt][1] * i0);
        *(float2*)(out + o0 + (size_t)8 * HH) = make_float2(O[nt][2] * i1, O[nt][3] * i1);
    }
}

// ---------------------------------------------------------------------------
extern "C" void kernel_launch(void* const* d_in, const int* in_sizes, int n_in,
                              void* d_out, int out_size)
{
    const float* x  = (const float*)d_in[0];
    const float* Wk = (const float*)d_in[1];
    const float* Wq = (const float*)d_in[2];
    const float* Wv = (const float*)d_in[3];
    float* out = (float*)d_out;

    proj_kernel<<<(BB * TT) / PM, 256>>>(x, Wk, Wq, Wv);

    cudaFuncSetAttribute(attn_kernel,
                         cudaFuncAttributeMaxDynamicSharedMemorySize,
                         ATTN_SMEM);
    attn_kernel<<<dim3(32, BB), 256, ATTN_SMEM>>>(out);
}

// round 8
// speedup vs baseline: 3.4210x; 1.1322x over previous
#include <cuda_runtime.h>
#include <math.h>
#include <stdint.h>

#define BB 4
#define TT 4096
#define CC 1024
#define HH 64

// Scratch for projected q,k,v (12 MB, __device__ globals per harness rules)
__device__ float g_q[(size_t)BB * TT * HH];
__device__ float g_k[(size_t)BB * TT * HH];
__device__ float g_v[(size_t)BB * TT * HH];

// ---------------------------------------------------------------------------
// tf32 helpers
// ---------------------------------------------------------------------------
__device__ __forceinline__ uint32_t f2tf(float f) {
    uint32_t u;
    asm("cvt.rna.tf32.f32 %0, %1;" : "=r"(u) : "f"(f));
    return u;
}

__device__ __forceinline__ uint4 f2tf4(float4 v) {
    uint4 u;
    u.x = f2tf(v.x); u.y = f2tf(v.y); u.z = f2tf(v.z); u.w = f2tf(v.w);
    return u;
}

// D = A(16x8, row) * B(8x8, col) + D, tf32 in, f32 accum.
__device__ __forceinline__ void mma8(float* c,
                                     uint32_t a0, uint32_t a1, uint32_t a2, uint32_t a3,
                                     uint32_t b0, uint32_t b1) {
    asm volatile(
        "mma.sync.aligned.m16n8k8.row.col.f32.tf32.tf32.f32 "
        "{%0,%1,%2,%3}, {%4,%5,%6,%7}, {%8,%9}, {%0,%1,%2,%3};"
        : "+f"(c[0]), "+f"(c[1]), "+f"(c[2]), "+f"(c[3])
        : "r"(a0), "r"(a1), "r"(a2), "r"(a3), "r"(b0), "r"(b1));
}

// ---------------------------------------------------------------------------
// Kernel 1: fused QKV projection, tf32 mma, k-chunk software pipeline.
// Block: 256 thr = 8 warps, tile M=128, N=64 (x3), K-chunks of 32.
// ---------------------------------------------------------------------------
#define PM  128
#define PKC 32
#define XP  36
#define WP  72
#define NKC (CC / PKC)

__global__ __launch_bounds__(256) void proj_kernel(
    const float* __restrict__ x,
    const float* __restrict__ Wk,
    const float* __restrict__ Wq,
    const float* __restrict__ Wv)
{
    __shared__ uint32_t Xs[PM * XP];
    __shared__ uint32_t Ws[3][PKC * WP];

    const int tid  = threadIdx.x;
    const int lane = tid & 31;
    const int wid  = tid >> 5;
    const int wm   = wid & 3;
    const int wn   = wid >> 2;
    const int g    = lane >> 2;
    const int t    = lane & 3;
    const int row0 = blockIdx.x * PM;
    const float* W[3] = {Wk, Wq, Wv};

    // Per-thread load slots: X 4 float4, W 2 float4 per matrix
    int xi[4], xc[4];
#pragma unroll
    for (int s = 0; s < 4; s++) {
        int idx = tid + s * 256;
        xi[s] = idx >> 3;
        xc[s] = (idx & 7) * 4;
    }
    int wr[2], wh[2];
#pragma unroll
    for (int s = 0; s < 2; s++) {
        int idx = tid + s * 256;
        wr[s] = idx >> 4;
        wh[s] = (idx & 15) * 4;
    }

    float acc[3][2][4][4];
#pragma unroll
    for (int m = 0; m < 3; m++)
#pragma unroll
        for (int mt = 0; mt < 2; mt++)
#pragma unroll
            for (int nt = 0; nt < 4; nt++)
#pragma unroll
                for (int e = 0; e < 4; e++) acc[m][mt][nt][e] = 0.f;

    float4 xbuf[4], wbuf[3][2];

    // Prologue: chunk 0 -> regs -> smem
#pragma unroll
    for (int s = 0; s < 4; s++)
        xbuf[s] = *(const float4*)(x + (size_t)(row0 + xi[s]) * CC + xc[s]);
#pragma unroll
    for (int s = 0; s < 2; s++)
#pragma unroll
        for (int m = 0; m < 3; m++)
            wbuf[m][s] = *(const float4*)(W[m] + (size_t)wr[s] * HH + wh[s]);
#pragma unroll
    for (int s = 0; s < 4; s++)
        *(uint4*)&Xs[xi[s] * XP + xc[s]] = f2tf4(xbuf[s]);
#pragma unroll
    for (int s = 0; s < 2; s++)
#pragma unroll
        for (int m = 0; m < 3; m++)
            *(uint4*)&Ws[m][wr[s] * WP + wh[s]] = f2tf4(wbuf[m][s]);
    __syncthreads();

    for (int kc = 0; kc < NKC; kc++) {
        const bool pf = (kc + 1) < NKC;
        if (pf) {
            const int kn = (kc + 1) * PKC;
#pragma unroll
            for (int s = 0; s < 4; s++)
                xbuf[s] = *(const float4*)(x + (size_t)(row0 + xi[s]) * CC + kn + xc[s]);
#pragma unroll
            for (int s = 0; s < 2; s++)
#pragma unroll
                for (int m = 0; m < 3; m++)
                    wbuf[m][s] = *(const float4*)(W[m] + (size_t)(kn + wr[s]) * HH + wh[s]);
        }

#pragma unroll
        for (int ks = 0; ks < 4; ks++) {
            const int k0 = ks * 8;
            uint32_t a[2][4];
#pragma unroll
            for (int mt = 0; mt < 2; mt++) {
                int ar = wm * 32 + mt * 16 + g;
                a[mt][0] = Xs[ar * XP + k0 + t];
                a[mt][1] = Xs[(ar + 8) * XP + k0 + t];
                a[mt][2] = Xs[ar * XP + k0 + t + 4];
                a[mt][3] = Xs[(ar + 8) * XP + k0 + t + 4];
            }
#pragma unroll
            for (int m = 0; m < 3; m++)
#pragma unroll
                for (int nt = 0; nt < 4; nt++) {
                    int n0 = wn * 32 + nt * 8;
                    uint32_t b0 = Ws[m][(k0 + t) * WP + n0 + g];
                    uint32_t b1 = Ws[m][(k0 + t + 4) * WP + n0 + g];
                    mma8(acc[m][0][nt], a[0][0], a[0][1], a[0][2], a[0][3], b0, b1);
                    mma8(acc[m][1][nt], a[1][0], a[1][1], a[1][2], a[1][3], b0, b1);
                }
        }

        if (pf) {
            __syncthreads();   // all warps done reading current chunk
#pragma unroll
            for (int s = 0; s < 4; s++)
                *(uint4*)&Xs[xi[s] * XP + xc[s]] = f2tf4(xbuf[s]);
#pragma unroll
            for (int s = 0; s < 2; s++)
#pragma unroll
                for (int m = 0; m < 3; m++)
                    *(uint4*)&Ws[m][wr[s] * WP + wh[s]] = f2tf4(wbuf[m][s]);
            __syncthreads();   // new chunk visible
        }
    }

    float* G[3] = {g_k, g_q, g_v};
#pragma unroll
    for (int m = 0; m < 3; m++)
#pragma unroll
        for (int mt = 0; mt < 2; mt++) {
            int r0 = row0 + wm * 32 + mt * 16 + g;
#pragma unroll
            for (int nt = 0; nt < 4; nt++) {
                int c0 = wn * 32 + nt * 8 + 2 * t;
                float* dst = G[m] + (size_t)r0 * HH + c0;
                *(float2*)dst = make_float2(acc[m][mt][nt][0], acc[m][mt][nt][1]);
                *(float2*)(dst + (size_t)8 * HH) =
                    make_float2(acc[m][mt][nt][2], acc[m][mt][nt][3]);
            }
        }
}

// ---------------------------------------------------------------------------
// Kernel 2: causal flash attention, tf32 mma, software-pipelined K/V.
// Block: 256 thr = 2 groups x 4 warps; group handles q-tile (p / 63-p)
// => every block does exactly 65 KV tiles. Double-buffered K/V in smem,
// gmem loads for tile kt+1 issued before computing tile kt.
// 2 named barriers per tile (128-thread groups).
// ---------------------------------------------------------------------------
#define QP 68
#define VP 72
// per group: Qs + K0 + K1 (QP pitch) + Ps + V0 + V1 (VP pitch)
#define GRP_U32 (64 * (4 * QP + 2 * VP))           // 26624 u32
#define ATTN_SMEM (2 * GRP_U32 * 4)                // 212992 bytes

__device__ __forceinline__ void group_bar(int id) {
    asm volatile("bar.sync %0, %1;" :: "r"(id), "r"(128) : "memory");
}

__global__ __launch_bounds__(256, 1) void attn_kernel(float* __restrict__ out)
{
    extern __shared__ uint32_t sm[];
    const int tid  = threadIdx.x;
    const int lane = tid & 31;
    const int wid  = tid >> 5;
    const int grp  = wid >> 2;
    const int lw   = wid & 3;
    const int gtid = tid & 127;
    const int g    = lane >> 2;
    const int t    = lane & 3;
    const int bar  = grp + 1;

    uint32_t* base = sm + grp * GRP_U32;
    uint32_t* Qs   = base;
    uint32_t* K0   = base + 64 * QP;
    uint32_t* K1   = base + 2 * 64 * QP;
    uint32_t* Ps   = base + 3 * 64 * QP;
    uint32_t* V0   = base + 4 * 64 * QP;
    uint32_t* V1   = base + 4 * 64 * QP + 64 * VP;

    const int b  = blockIdx.y;
    const int p  = blockIdx.x;              // 0..31
    const int qt = grp ? (63 - p) : p;
    const int qrow0 = qt * 64;
    const float scale = 0.03125f;           // 1024^-0.5

    // Per-thread load slots for 64x64 tiles: 8 float4 each
    int li[8], lh[8];
#pragma unroll
    for (int s = 0; s < 8; s++) {
        int idx = gtid + s * 128;
        li[s] = idx >> 4;
        lh[s] = (idx & 15) * 4;
    }

    // Load Q (pre-scaled, tf32) and tile 0 K/V into buffer 0
#pragma unroll
    for (int s = 0; s < 8; s++) {
        float4 qv = *(const float4*)(g_q + ((size_t)b * TT + qrow0 + li[s]) * HH + lh[s]);
        qv.x *= scale; qv.y *= scale; qv.z *= scale; qv.w *= scale;
        *(uint4*)&Qs[li[s] * QP + lh[s]] = f2tf4(qv);
    }
#pragma unroll
    for (int s = 0; s < 8; s++) {
        size_t go = ((size_t)b * TT + li[s]) * HH + lh[s];
        *(uint4*)&K0[li[s] * QP + lh[s]] = f2tf4(*(const float4*)(g_k + go));
        *(uint4*)&V0[li[s] * VP + lh[s]] = f2tf4(*(const float4*)(g_v + go));
    }
    group_bar(bar);

    float m0v = -INFINITY, m1v = -INFINITY, l0 = 0.f, l1 = 0.f;
    float O[8][4];
#pragma unroll
    for (int nt = 0; nt < 8; nt++)
#pragma unroll
        for (int e = 0; e < 4; e++) O[nt][e] = 0.f;

    const int arow = lw * 16 + g;
    int pb = 0;                              // current buffer parity

    for (int kt = 0; kt <= qt; kt++) {
        uint32_t* Kc = pb ? K1 : K0;
        uint32_t* Vc = pb ? V1 : V0;
        uint32_t* Kn = pb ? K0 : K1;
        uint32_t* Vn = pb ? V0 : V1;

        // Prefetch tile kt+1 into registers (latency overlapped with S+softmax)
        const bool pf = kt < qt;
        float4 kbuf[8], vbuf[8];
        if (pf) {
            const size_t rb = (size_t)b * TT + (size_t)(kt + 1) * 64;
#pragma unroll
            for (int s = 0; s < 8; s++) {
                size_t go = (rb + li[s]) * HH + lh[s];
                kbuf[s] = *(const float4*)(g_k + go);
                vbuf[s] = *(const float4*)(g_v + go);
            }
        }

        // S = Qs * Kc^T
        float S[8][4];
#pragma unroll
        for (int nt = 0; nt < 8; nt++)
#pragma unroll
            for (int e = 0; e < 4; e++) S[nt][e] = 0.f;

#pragma unroll
        for (int ks = 0; ks < 8; ks++) {
            const int k0 = ks * 8;
            uint32_t a0 = Qs[arow * QP + k0 + t];
            uint32_t a1 = Qs[(arow + 8) * QP + k0 + t];
            uint32_t a2 = Qs[arow * QP + k0 + t + 4];
            uint32_t a3 = Qs[(arow + 8) * QP + k0 + t + 4];
#pragma unroll
            for (int nt = 0; nt < 8; nt++) {
                uint32_t b0 = Kc[(nt * 8 + g) * QP + k0 + t];
                uint32_t b1 = Kc[(nt * 8 + g) * QP + k0 + t + 4];
                mma8(S[nt], a0, a1, a2, a3, b0, b1);
            }
        }

        // Causal mask (diagonal tile only)
        if (kt == qt) {
            const int krow0 = kt * 64;
            int r0 = qrow0 + arow, r1 = r0 + 8;
#pragma unroll
            for (int nt = 0; nt < 8; nt++) {
                int c = krow0 + nt * 8 + 2 * t;
                if (c     > r0) S[nt][0] = -INFINITY;
                if (c + 1 > r0) S[nt][1] = -INFINITY;
                if (c     > r1) S[nt][2] = -INFINITY;
                if (c + 1 > r1) S[nt][3] = -INFINITY;
            }
        }

        // Row max (lane-quad reduce)
        float mt0 = -INFINITY, mt1 = -INFINITY;
#pragma unroll
        for (int nt = 0; nt < 8; nt++) {
            mt0 = fmaxf(mt0, fmaxf(S[nt][0], S[nt][1]));
            mt1 = fmaxf(mt1, fmaxf(S[nt][2], S[nt][3]));
        }
        mt0 = fmaxf(mt0, __shfl_xor_sync(0xffffffffu, mt0, 1));
        mt0 = fmaxf(mt0, __shfl_xor_sync(0xffffffffu, mt0, 2));
        mt1 = fmaxf(mt1, __shfl_xor_sync(0xffffffffu, mt1, 1));
        mt1 = fmaxf(mt1, __shfl_xor_sync(0xffffffffu, mt1, 2));

        float mn0 = fmaxf(m0v, mt0), mn1 = fmaxf(m1v, mt1);
        float cr0 = __expf(m0v - mn0), cr1 = __expf(m1v - mn1);

        // P = exp(S - mn) -> Ps (tf32), row sums
        float rs0 = 0.f, rs1 = 0.f;
#pragma unroll
        for (int nt = 0; nt < 8; nt++) {
            float p0 = __expf(S[nt][0] - mn0);
            float p1 = __expf(S[nt][1] - mn0);
            float p2 = __expf(S[nt][2] - mn1);
            float p3 = __expf(S[nt][3] - mn1);
            rs0 += p0 + p1;
            rs1 += p2 + p3;
            uint2 u01; u01.x = f2tf(p0); u01.y = f2tf(p1);
            uint2 u23; u23.x = f2tf(p2); u23.y = f2tf(p3);
            *(uint2*)&Ps[arow * QP + nt * 8 + 2 * t]       = u01;
            *(uint2*)&Ps[(arow + 8) * QP + nt * 8 + 2 * t] = u23;
        }
        rs0 += __shfl_xor_sync(0xffffffffu, rs0, 1);
        rs0 += __shfl_xor_sync(0xffffffffu, rs0, 2);
        rs1 += __shfl_xor_sync(0xffffffffu, rs1, 1);
        rs1 += __shfl_xor_sync(0xffffffffu, rs1, 2);

        l0 = l0 * cr0 + rs0;
        l1 = l1 * cr1 + rs1;
        m0v = mn0; m1v = mn1;
#pragma unroll
        for (int nt = 0; nt < 8; nt++) {
            O[nt][0] *= cr0; O[nt][1] *= cr0;
            O[nt][2] *= cr1; O[nt][3] *= cr1;
        }
        group_bar(bar);   // Ps visible to group; buffer 1-pb free (PV kt-1 done)

        // Stage prefetched tile kt+1 into the alternate buffers
        if (pf) {
#pragma unroll
            for (int s = 0; s < 8; s++) {
                *(uint4*)&Kn[li[s] * QP + lh[s]] = f2tf4(kbuf[s]);
                *(uint4*)&Vn[li[s] * VP + lh[s]] = f2tf4(vbuf[s]);
            }
        }

        // O += Ps * Vc
#pragma unroll
        for (int ks = 0; ks < 8; ks++) {
            const int k0 = ks * 8;
            uint32_t a0 = Ps[arow * QP + k0 + t];
            uint32_t a1 = Ps[(arow + 8) * QP + k0 + t];
            uint32_t a2 = Ps[arow * QP + k0 + t + 4];
            uint32_t a3 = Ps[(arow + 8) * QP + k0 + t + 4];
#pragma unroll
            for (int nt = 0; nt < 8; nt++) {
                uint32_t b0 = Vc[(k0 + t) * VP + nt * 8 + g];
                uint32_t b1 = Vc[(k0 + t + 4) * VP + nt * 8 + g];
                mma8(O[nt], a0, a1, a2, a3, b0, b1);
            }
        }
        group_bar(bar);   // PV done (Ps, Vc free), next K/V staged
        pb ^= 1;
    }

    // Normalize and write
    float i0 = 1.0f / l0, i1 = 1.0f / l1;
    const int r0 = qrow0 + arow;
#pragma unroll
    for (int nt = 0; nt < 8; nt++) {
        size_t o0 = ((size_t)b * TT + r0) * HH + nt * 8 + 2 * t;
        *(float2*)(out + o0)                  = make_float2(O[nt][0] * i0, O[nt][1] * i0);
        *(float2*)(out + o0 + (size_t)8 * HH) = make_float2(O[nt][2] * i1, O[nt][3] * i1);
    }
}

// ---------------------------------------------------------------------------
extern "C" void kernel_launch(void* const* d_in, const int* in_sizes, int n_in,
                              void* d_out, int out_size)
{
    const float* x  = (const float*)d_in[0];
    const float* Wk = (const float*)d_in[1];
    const float* Wq = (const float*)d_in[2];
    const float* Wv = (const float*)d_in[3];
    float* out = (float*)d_out;

    proj_kernel<<<(BB * TT) / PM, 256>>>(x, Wk, Wq, Wv);

    cudaFuncSetAttribute(attn_kernel,
                         cudaFuncAttributeMaxDynamicSharedMemorySize,
                         ATTN_SMEM);
    attn_kernel<<<dim3(32, BB), 256, ATTN_SMEM>>>(out);
}